// round 1
// baseline (speedup 1.0000x reference)
#include <cuda_runtime.h>
#include <math.h>

#define NR 2048      // batch*tlen rows
#define DK 1024      // input dim
#define VO 32000     // vocab
#define SL 512       // slen
#define NB 32        // batch
#define CV 500       // copy vocab
#define OC 32500     // output cols

// ---------------- scratch (device globals; no allocations allowed) ----------
static __device__ float g_Mx[(size_t)NR * VO];   // 262 MB GEMM output
static __device__ float g_xnorm[NR];
static __device__ float g_pcopy[NR];
static __device__ float g_gamma[NR];
static __device__ float g_delta[NR];
static __device__ float g_rowmax[NR];
static __device__ float g_rowsum[NR];
static __device__ float g_y2;                    // ||b||^2

// ---------------- helpers ----------------
__device__ __forceinline__ float block_reduce_sum(float v, float* sbuf) {
    int tid = threadIdx.x;
    sbuf[tid] = v;
    __syncthreads();
    #pragma unroll
    for (int off = 128; off > 0; off >>= 1) {
        if (tid < off) sbuf[tid] += sbuf[tid + off];
        __syncthreads();
    }
    float r = sbuf[0];
    __syncthreads();
    return r;
}

// ---------------- ||b||^2 ----------------
__global__ void __launch_bounds__(256) bnorm_kernel(const float* __restrict__ b) {
    __shared__ float sbuf[256];
    float s = 0.f;
    for (int i = threadIdx.x; i < VO; i += 256) { float v = b[i]; s += v * v; }
    s = block_reduce_sum(s, sbuf);
    if (threadIdx.x == 0) g_y2 = s;
}

// --------- per-row: x_norm, p_copy (V=1 mobius head + sigmoid) ---------
__global__ void __launch_bounds__(256) row_prep_kernel(const float* __restrict__ hidden,
                                                       const float* __restrict__ Wc,
                                                       const float* __restrict__ bcp) {
    __shared__ float s1[256];
    __shared__ float s2[256];
    int row = blockIdx.x;
    const float4* h4 = (const float4*)(hidden + (size_t)row * DK);
    const float4* w4 = (const float4*)Wc;
    int i = threadIdx.x;           // exactly DK/4 = 256 vec elems
    float4 h = h4[i];
    float4 w = w4[i];
    float ss = h.x * h.x + h.y * h.y + h.z * h.z + h.w * h.w;
    float sm = h.x * w.x + h.y * w.y + h.z * w.z + h.w * w.w;
    ss = block_reduce_sum(ss, s1);
    sm = block_reduce_sum(sm, s2);
    if (threadIdx.x == 0) {
        float xn = fmaxf(sqrtf(ss), 1e-15f);
        g_xnorm[row] = xn;
        float art = atanhf(fminf(xn, 1.f - 1e-7f));
        float mn = fmaxf(fabsf(sm), 1e-15f);
        float t1 = tanhf(mn / xn * art) * (sm / mn);
        float bc = *bcp;
        float y2 = bc * bc, x2 = t1 * t1, xy = t1 * bc;
        float num = (1.f + 2.f * xy + y2) * t1 + (1.f - x2) * bc;
        float den = fmaxf(1.f + 2.f * xy + x2 * y2, 1e-15f);
        float u = num / den;
        float au = fmaxf(fabsf(u), 1e-15f);
        if (au > 0.996f) u = u / au * 0.996f;
        g_pcopy[row] = 1.f / (1.f + expf(-u));
    }
}

// ---------------- big GEMM: g_Mx = hidden @ W^T ----------------
#define BM 128
#define BN 128
#define BK 16
__global__ void __launch_bounds__(256) gemm_kernel(const float* __restrict__ A,
                                                   const float* __restrict__ W) {
    __shared__ __align__(16) float As[BK][BM];   // transposed A tile
    __shared__ __align__(16) float Bs[BK][BN];   // transposed W tile
    const int row0 = blockIdx.y * BM;
    const int col0 = blockIdx.x * BN;
    const int tid = threadIdx.x;
    const int tx = tid % 16;       // n dir
    const int ty = tid / 16;       // m dir
    const int lr = tid / 4;        // 0..63
    const int lc = tid % 4;        // float4 slot in BK

    float acc[8][8] = {};

    for (int k0 = 0; k0 < DK; k0 += BK) {
        float4 a0 = *(const float4*)(A + (size_t)(row0 + lr) * DK + k0 + lc * 4);
        float4 a1 = *(const float4*)(A + (size_t)(row0 + lr + 64) * DK + k0 + lc * 4);
        float4 b0 = *(const float4*)(W + (size_t)(col0 + lr) * DK + k0 + lc * 4);
        float4 b1 = *(const float4*)(W + (size_t)(col0 + lr + 64) * DK + k0 + lc * 4);
        __syncthreads();
        As[lc * 4 + 0][lr] = a0.x; As[lc * 4 + 1][lr] = a0.y;
        As[lc * 4 + 2][lr] = a0.z; As[lc * 4 + 3][lr] = a0.w;
        As[lc * 4 + 0][lr + 64] = a1.x; As[lc * 4 + 1][lr + 64] = a1.y;
        As[lc * 4 + 2][lr + 64] = a1.z; As[lc * 4 + 3][lr + 64] = a1.w;
        Bs[lc * 4 + 0][lr] = b0.x; Bs[lc * 4 + 1][lr] = b0.y;
        Bs[lc * 4 + 2][lr] = b0.z; Bs[lc * 4 + 3][lr] = b0.w;
        Bs[lc * 4 + 0][lr + 64] = b1.x; Bs[lc * 4 + 1][lr + 64] = b1.y;
        Bs[lc * 4 + 2][lr + 64] = b1.z; Bs[lc * 4 + 3][lr + 64] = b1.w;
        __syncthreads();
        #pragma unroll
        for (int k = 0; k < BK; k++) {
            float a[8], b[8];
            *(float4*)&a[0] = *(const float4*)&As[k][ty * 8];
            *(float4*)&a[4] = *(const float4*)&As[k][ty * 8 + 4];
            *(float4*)&b[0] = *(const float4*)&Bs[k][tx * 8];
            *(float4*)&b[4] = *(const float4*)&Bs[k][tx * 8 + 4];
            #pragma unroll
            for (int i = 0; i < 8; i++)
                #pragma unroll
                for (int j = 0; j < 8; j++)
                    acc[i][j] = fmaf(a[i], b[j], acc[i][j]);
        }
    }

    #pragma unroll
    for (int i = 0; i < 8; i++) {
        float* cp = g_Mx + (size_t)(row0 + ty * 8 + i) * VO + col0 + tx * 8;
        *(float4*)cp       = *(float4*)&acc[i][0];
        *(float4*)(cp + 4) = *(float4*)&acc[i][4];
    }
}

// ------- per-row reductions over Mx -> gamma, delta (fused mobius chain) -----
__global__ void __launch_bounds__(256) rowred_kernel(const float* __restrict__ b) {
    __shared__ float s1[256];
    __shared__ float s2[256];
    int row = blockIdx.x;
    const float4* mx4 = (const float4*)(g_Mx + (size_t)row * VO);
    const float4* b4 = (const float4*)b;
    float ss = 0.f, db = 0.f;
    for (int i = threadIdx.x; i < VO / 4; i += 256) {
        float4 x = mx4[i];
        float4 y = b4[i];
        ss += x.x * x.x + x.y * x.y + x.z * x.z + x.w * x.w;
        db += x.x * y.x + x.y * y.y + x.z * y.z + x.w * y.w;
    }
    ss = block_reduce_sum(ss, s1);
    db = block_reduce_sum(db, s2);
    if (threadIdx.x == 0) {
        float xn = g_xnorm[row];
        float mxn = fmaxf(sqrtf(ss), 1e-15f);
        float art = atanhf(fminf(xn, 1.f - 1e-7f));
        float t = tanhf(mxn / xn * art);
        float alpha = t / mxn;
        float xy = alpha * db;
        float x2 = t * t;
        float y2 = g_y2;
        float Ac = 1.f + 2.f * xy + y2;
        float Bc = 1.f - x2;
        float den = fmaxf(1.f + 2.f * xy + x2 * y2, 1e-15f);
        float g0 = Ac * alpha / den;
        float d0 = Bc / den;
        // analytic ||logits|| for project()
        float nl2 = (Ac * Ac * t * t + 2.f * Ac * Bc * alpha * db + Bc * Bc * y2) / (den * den);
        float nl = fmaxf(sqrtf(nl2), 1e-15f);
        float sc = (nl > 0.996f) ? (0.996f / nl) : 1.f;
        g_gamma[row] = sc * g0;
        g_delta[row] = sc * d0;
    }
}

// ------- online softmax pass: rowmax + sumexp (pad skipped) -------
__global__ void __launch_bounds__(256) softmax_kernel(const float* __restrict__ b,
                                                      const int* __restrict__ padp) {
    __shared__ float sm[256];
    __shared__ float ssum[256];
    int row = blockIdx.x;
    int pad = *padp;
    const float* mx = g_Mx + (size_t)row * VO;
    float gamma = g_gamma[row], delta = g_delta[row];
    float m = -INFINITY, s = 0.f;
    for (int i = threadIdx.x; i < VO; i += 256) {
        if (i == pad) continue;
        float l = gamma * mx[i] + delta * b[i];
        if (l > m) { s = s * expf(m - l) + 1.f; m = l; }
        else       { s += expf(l - m); }
    }
    int tid = threadIdx.x;
    sm[tid] = m; ssum[tid] = s;
    __syncthreads();
    #pragma unroll
    for (int off = 128; off > 0; off >>= 1) {
        if (tid < off) {
            float m2 = sm[tid + off], s2 = ssum[tid + off];
            float mn = fmaxf(sm[tid], m2);
            ssum[tid] = ssum[tid] * expf(sm[tid] - mn) + s2 * expf(m2 - mn);
            sm[tid] = mn;
        }
        __syncthreads();
    }
    if (tid == 0) { g_rowmax[row] = sm[0]; g_rowsum[row] = ssum[0]; }
}

// ------- write out_prob = softmax * (1 - p_copy) -------
__global__ void __launch_bounds__(256) writeout_kernel(const float* __restrict__ b,
                                                       const int* __restrict__ padp,
                                                       float* __restrict__ out) {
    int row = blockIdx.x;
    int pad = *padp;
    const float4* mx4 = (const float4*)(g_Mx + (size_t)row * VO);
    const float4* b4 = (const float4*)b;
    float gamma = g_gamma[row], delta = g_delta[row];
    float m = g_rowmax[row];
    float inv = (1.f - g_pcopy[row]) / g_rowsum[row];
    float4* o4 = (float4*)(out + (size_t)row * OC);
    for (int i = threadIdx.x; i < VO / 4; i += 256) {
        float4 x = mx4[i];
        float4 bb = b4[i];
        float4 r;
        r.x = expf(gamma * x.x + delta * bb.x - m) * inv;
        r.y = expf(gamma * x.y + delta * bb.y - m) * inv;
        r.z = expf(gamma * x.z + delta * bb.z - m) * inv;
        r.w = expf(gamma * x.w + delta * bb.w - m) * inv;
        int base = i * 4;
        if (pad >= base && pad < base + 4) ((float*)&r)[pad - base] = 0.f;
        o4[i] = r;
    }
}

// ------- copy branch: per-batch (64x512)@(512x500) small GEMM -------
#define SCH 32
__global__ void __launch_bounds__(256) copy_kernel(const float* __restrict__ attn,
                                                   const float* __restrict__ src,
                                                   float* __restrict__ out) {
    __shared__ float sa[64][SCH + 1];   // [t][s], padded
    __shared__ float sb[SCH][128];      // [s][c]
    __shared__ float spc[64];
    const int bb = blockIdx.y;
    const int c0 = blockIdx.x * 128;
    const int tid = threadIdx.x;
    const int tx = tid % 16;            // c groups of 8
    const int ty = tid / 16;            // t groups of 4

    if (tid < 64) spc[tid] = g_pcopy[tid * NB + bb];

    float acc[4][8] = {};
    for (int s0 = 0; s0 < SL; s0 += SCH) {
        __syncthreads();
        // load attn tile * p_copy : 64 x 32
        for (int i = tid; i < 64 * (SCH / 4); i += 256) {
            int t = i / (SCH / 4);
            int sv = i % (SCH / 4);
            float4 v = *(const float4*)(attn + (size_t)(t * NB + bb) * SL + s0 + sv * 4);
            float pc = spc[t];
            sa[t][sv * 4 + 0] = v.x * pc;
            sa[t][sv * 4 + 1] = v.y * pc;
            sa[t][sv * 4 + 2] = v.z * pc;
            sa[t][sv * 4 + 3] = v.w * pc;
        }
        // load src_map tile : 32 x 128 (guarded at c>=500)
        for (int i = tid; i < SCH * 128; i += 256) {
            int s = i / 128;
            int c = i % 128;
            int cg = c0 + c;
            sb[s][c] = (cg < CV) ? src[(size_t)(s0 + s) * (NB * CV) + bb * CV + cg] : 0.f;
        }
        __syncthreads();
        #pragma unroll 8
        for (int s = 0; s < SCH; s++) {
            float a[4], bf[8];
            #pragma unroll
            for (int i = 0; i < 4; i++) a[i] = sa[ty * 4 + i][s];
            #pragma unroll
            for (int j = 0; j < 8; j++) bf[j] = sb[s][tx * 8 + j];
            #pragma unroll
            for (int i = 0; i < 4; i++)
                #pragma unroll
                for (int j = 0; j < 8; j++)
                    acc[i][j] = fmaf(a[i], bf[j], acc[i][j]);
        }
    }
    #pragma unroll
    for (int i = 0; i < 4; i++) {
        int t = ty * 4 + i;
        #pragma unroll
        for (int j = 0; j < 8; j++) {
            int c = c0 + tx * 8 + j;
            if (c < CV)
                out[(size_t)(t * NB + bb) * OC + VO + c] = acc[i][j];
        }
    }
}

// ---------------- launch ----------------
extern "C" void kernel_launch(void* const* d_in, const int* in_sizes, int n_in,
                              void* d_out, int out_size) {
    const float* hidden = (const float*)d_in[0];
    const float* attn   = (const float*)d_in[1];
    const float* srcm   = (const float*)d_in[2];
    const float* W      = (const float*)d_in[3];
    const float* b      = (const float*)d_in[4];
    const float* Wc     = (const float*)d_in[5];
    const float* bc     = (const float*)d_in[6];
    const int*   pad    = (const int*)d_in[7];
    float* out = (float*)d_out;

    bnorm_kernel<<<1, 256>>>(b);
    row_prep_kernel<<<NR, 256>>>(hidden, Wc, bc);
    gemm_kernel<<<dim3(VO / BN, NR / BM), 256>>>(hidden, W);
    rowred_kernel<<<NR, 256>>>(b);
    softmax_kernel<<<NR, 256>>>(b, pad);
    writeout_kernel<<<NR, 256>>>(b, pad, out);
    copy_kernel<<<dim3((CV + 127) / 128, NB), 256>>>(attn, srcm, out);
}

// round 2
// speedup vs baseline: 1.0018x; 1.0018x over previous
#include <cuda_runtime.h>
#include <math.h>

#define NR 2048      // batch*tlen rows
#define DK 1024      // input dim
#define VO 32000     // vocab
#define SL 512       // slen
#define NB 32        // batch
#define CV 500       // copy vocab
#define OC 32500     // output cols

// ---------------- scratch (device globals; no allocations allowed) ----------
static __device__ float g_Mx[(size_t)NR * VO];   // 262 MB GEMM output
static __device__ float g_xnorm[NR];
static __device__ float g_pcopy[NR];
static __device__ float g_gamma[NR];
static __device__ float g_delta[NR];
static __device__ float g_rowmax[NR];
static __device__ float g_rowsum[NR];
static __device__ float g_y2;                    // ||b||^2

// ---------------- helpers ----------------
__device__ __forceinline__ float block_reduce_sum(float v, float* sbuf) {
    int tid = threadIdx.x;
    sbuf[tid] = v;
    __syncthreads();
    #pragma unroll
    for (int off = 128; off > 0; off >>= 1) {
        if (tid < off) sbuf[tid] += sbuf[tid + off];
        __syncthreads();
    }
    float r = sbuf[0];
    __syncthreads();
    return r;
}

// ---------------- ||b||^2 ----------------
__global__ void __launch_bounds__(256) bnorm_kernel(const float* __restrict__ b) {
    __shared__ float sbuf[256];
    float s = 0.f;
    for (int i = threadIdx.x; i < VO; i += 256) { float v = b[i]; s += v * v; }
    s = block_reduce_sum(s, sbuf);
    if (threadIdx.x == 0) g_y2 = s;
}

// --------- per-row: x_norm, p_copy (V=1 mobius head + sigmoid) ---------
__global__ void __launch_bounds__(256) row_prep_kernel(const float* __restrict__ hidden,
                                                       const float* __restrict__ Wc,
                                                       const float* __restrict__ bcp) {
    __shared__ float s1[256];
    __shared__ float s2[256];
    int row = blockIdx.x;
    const float4* h4 = (const float4*)(hidden + (size_t)row * DK);
    const float4* w4 = (const float4*)Wc;
    int i = threadIdx.x;           // exactly DK/4 = 256 vec elems
    float4 h = h4[i];
    float4 w = w4[i];
    float ss = h.x * h.x + h.y * h.y + h.z * h.z + h.w * h.w;
    float sm = h.x * w.x + h.y * w.y + h.z * w.z + h.w * w.w;
    ss = block_reduce_sum(ss, s1);
    sm = block_reduce_sum(sm, s2);
    if (threadIdx.x == 0) {
        float xn = fmaxf(sqrtf(ss), 1e-15f);
        g_xnorm[row] = xn;
        float art = atanhf(fminf(xn, 1.f - 1e-7f));
        float mn = fmaxf(fabsf(sm), 1e-15f);
        float t1 = tanhf(mn / xn * art) * (sm / mn);
        float bc = *bcp;
        float y2 = bc * bc, x2 = t1 * t1, xy = t1 * bc;
        float num = (1.f + 2.f * xy + y2) * t1 + (1.f - x2) * bc;
        float den = fmaxf(1.f + 2.f * xy + x2 * y2, 1e-15f);
        float u = num / den;
        float au = fmaxf(fabsf(u), 1e-15f);
        if (au > 0.996f) u = u / au * 0.996f;
        g_pcopy[row] = 1.f / (1.f + expf(-u));
    }
}

// ---------------- big GEMM: g_Mx = hidden @ W^T ----------------
#define BM 128
#define BN 128
#define BK 16
__global__ void __launch_bounds__(256) gemm_kernel(const float* __restrict__ A,
                                                   const float* __restrict__ W) {
    __shared__ __align__(16) float As[BK][BM];   // transposed A tile
    __shared__ __align__(16) float Bs[BK][BN];   // transposed W tile
    const int row0 = blockIdx.y * BM;
    const int col0 = blockIdx.x * BN;
    const int tid = threadIdx.x;
    const int tx = tid % 16;       // n dir
    const int ty = tid / 16;       // m dir
    const int lr = tid / 4;        // 0..63
    const int lc = tid % 4;        // float4 slot in BK

    float acc[8][8] = {};

    for (int k0 = 0; k0 < DK; k0 += BK) {
        float4 a0 = *(const float4*)(A + (size_t)(row0 + lr) * DK + k0 + lc * 4);
        float4 a1 = *(const float4*)(A + (size_t)(row0 + lr + 64) * DK + k0 + lc * 4);
        float4 b0 = *(const float4*)(W + (size_t)(col0 + lr) * DK + k0 + lc * 4);
        float4 b1 = *(const float4*)(W + (size_t)(col0 + lr + 64) * DK + k0 + lc * 4);
        __syncthreads();
        As[lc * 4 + 0][lr] = a0.x; As[lc * 4 + 1][lr] = a0.y;
        As[lc * 4 + 2][lr] = a0.z; As[lc * 4 + 3][lr] = a0.w;
        As[lc * 4 + 0][lr + 64] = a1.x; As[lc * 4 + 1][lr + 64] = a1.y;
        As[lc * 4 + 2][lr + 64] = a1.z; As[lc * 4 + 3][lr + 64] = a1.w;
        Bs[lc * 4 + 0][lr] = b0.x; Bs[lc * 4 + 1][lr] = b0.y;
        Bs[lc * 4 + 2][lr] = b0.z; Bs[lc * 4 + 3][lr] = b0.w;
        Bs[lc * 4 + 0][lr + 64] = b1.x; Bs[lc * 4 + 1][lr + 64] = b1.y;
        Bs[lc * 4 + 2][lr + 64] = b1.z; Bs[lc * 4 + 3][lr + 64] = b1.w;
        __syncthreads();
        #pragma unroll
        for (int k = 0; k < BK; k++) {
            float a[8], b[8];
            *(float4*)&a[0] = *(const float4*)&As[k][ty * 8];
            *(float4*)&a[4] = *(const float4*)&As[k][ty * 8 + 4];
            *(float4*)&b[0] = *(const float4*)&Bs[k][tx * 8];
            *(float4*)&b[4] = *(const float4*)&Bs[k][tx * 8 + 4];
            #pragma unroll
            for (int i = 0; i < 8; i++)
                #pragma unroll
                for (int j = 0; j < 8; j++)
                    acc[i][j] = fmaf(a[i], b[j], acc[i][j]);
        }
    }

    #pragma unroll
    for (int i = 0; i < 8; i++) {
        float* cp = g_Mx + (size_t)(row0 + ty * 8 + i) * VO + col0 + tx * 8;
        *(float4*)cp       = *(float4*)&acc[i][0];
        *(float4*)(cp + 4) = *(float4*)&acc[i][4];
    }
}

// ------- per-row reductions over Mx -> gamma, delta (fused mobius chain) -----
__global__ void __launch_bounds__(256) rowred_kernel(const float* __restrict__ b) {
    __shared__ float s1[256];
    __shared__ float s2[256];
    int row = blockIdx.x;
    const float4* mx4 = (const float4*)(g_Mx + (size_t)row * VO);
    const float4* b4 = (const float4*)b;
    float ss = 0.f, db = 0.f;
    for (int i = threadIdx.x; i < VO / 4; i += 256) {
        float4 x = mx4[i];
        float4 y = b4[i];
        ss += x.x * x.x + x.y * x.y + x.z * x.z + x.w * x.w;
        db += x.x * y.x + x.y * y.y + x.z * y.z + x.w * y.w;
    }
    ss = block_reduce_sum(ss, s1);
    db = block_reduce_sum(db, s2);
    if (threadIdx.x == 0) {
        float xn = g_xnorm[row];
        float mxn = fmaxf(sqrtf(ss), 1e-15f);
        float art = atanhf(fminf(xn, 1.f - 1e-7f));
        float t = tanhf(mxn / xn * art);
        float alpha = t / mxn;
        float xy = alpha * db;
        float x2 = t * t;
        float y2 = g_y2;
        float Ac = 1.f + 2.f * xy + y2;
        float Bc = 1.f - x2;
        float den = fmaxf(1.f + 2.f * xy + x2 * y2, 1e-15f);
        float g0 = Ac * alpha / den;
        float d0 = Bc / den;
        // analytic ||logits|| for project()
        float nl2 = (Ac * Ac * t * t + 2.f * Ac * Bc * alpha * db + Bc * Bc * y2) / (den * den);
        float nl = fmaxf(sqrtf(nl2), 1e-15f);
        float sc = (nl > 0.996f) ? (0.996f / nl) : 1.f;
        g_gamma[row] = sc * g0;
        g_delta[row] = sc * d0;
    }
}

// ------- online softmax pass: rowmax + sumexp (pad skipped) -------
__global__ void __launch_bounds__(256) softmax_kernel(const float* __restrict__ b,
                                                      const int* __restrict__ padp) {
    __shared__ float sm[256];
    __shared__ float ssum[256];
    int row = blockIdx.x;
    int pad = *padp;
    const float* mx = g_Mx + (size_t)row * VO;
    float gamma = g_gamma[row], delta = g_delta[row];
    float m = -INFINITY, s = 0.f;
    for (int i = threadIdx.x; i < VO; i += 256) {
        if (i == pad) continue;
        float l = gamma * mx[i] + delta * b[i];
        if (l > m) { s = s * expf(m - l) + 1.f; m = l; }
        else       { s += expf(l - m); }
    }
    int tid = threadIdx.x;
    sm[tid] = m; ssum[tid] = s;
    __syncthreads();
    #pragma unroll
    for (int off = 128; off > 0; off >>= 1) {
        if (tid < off) {
            float m2 = sm[tid + off], s2 = ssum[tid + off];
            float mn = fmaxf(sm[tid], m2);
            ssum[tid] = ssum[tid] * expf(sm[tid] - mn) + s2 * expf(m2 - mn);
            sm[tid] = mn;
        }
        __syncthreads();
    }
    if (tid == 0) { g_rowmax[row] = sm[0]; g_rowsum[row] = ssum[0]; }
}

// ------- write out_prob = softmax * (1 - p_copy) -------
__global__ void __launch_bounds__(256) writeout_kernel(const float* __restrict__ b,
                                                       const int* __restrict__ padp,
                                                       float* __restrict__ out) {
    int row = blockIdx.x;
    int pad = *padp;
    const float4* mx4 = (const float4*)(g_Mx + (size_t)row * VO);
    const float4* b4 = (const float4*)b;
    float gamma = g_gamma[row], delta = g_delta[row];
    float m = g_rowmax[row];
    float inv = (1.f - g_pcopy[row]) / g_rowsum[row];
    float4* o4 = (float4*)(out + (size_t)row * OC);
    for (int i = threadIdx.x; i < VO / 4; i += 256) {
        float4 x = mx4[i];
        float4 bb = b4[i];
        float4 r;
        r.x = expf(gamma * x.x + delta * bb.x - m) * inv;
        r.y = expf(gamma * x.y + delta * bb.y - m) * inv;
        r.z = expf(gamma * x.z + delta * bb.z - m) * inv;
        r.w = expf(gamma * x.w + delta * bb.w - m) * inv;
        int base = i * 4;
        if (pad >= base && pad < base + 4) ((float*)&r)[pad - base] = 0.f;
        o4[i] = r;
    }
}

// ------- copy branch: per-batch (64x512)@(512x500) small GEMM -------
#define SCH 32
__global__ void __launch_bounds__(256) copy_kernel(const float* __restrict__ attn,
                                                   const float* __restrict__ src,
                                                   float* __restrict__ out) {
    __shared__ float sa[64][SCH + 1];   // [t][s], padded
    __shared__ float sb[SCH][128];      // [s][c]
    __shared__ float spc[64];
    const int bb = blockIdx.y;
    const int c0 = blockIdx.x * 128;
    const int tid = threadIdx.x;
    const int tx = tid % 16;            // c groups of 8
    const int ty = tid / 16;            // t groups of 4

    if (tid < 64) spc[tid] = g_pcopy[tid * NB + bb];

    float acc[4][8] = {};
    for (int s0 = 0; s0 < SL; s0 += SCH) {
        __syncthreads();
        // load attn tile * p_copy : 64 x 32
        for (int i = tid; i < 64 * (SCH / 4); i += 256) {
            int t = i / (SCH / 4);
            int sv = i % (SCH / 4);
            float4 v = *(const float4*)(attn + (size_t)(t * NB + bb) * SL + s0 + sv * 4);
            float pc = spc[t];
            sa[t][sv * 4 + 0] = v.x * pc;
            sa[t][sv * 4 + 1] = v.y * pc;
            sa[t][sv * 4 + 2] = v.z * pc;
            sa[t][sv * 4 + 3] = v.w * pc;
        }
        // load src_map tile : 32 x 128 (guarded at c>=500)
        for (int i = tid; i < SCH * 128; i += 256) {
            int s = i / 128;
            int c = i % 128;
            int cg = c0 + c;
            sb[s][c] = (cg < CV) ? src[(size_t)(s0 + s) * (NB * CV) + bb * CV + cg] : 0.f;
        }
        __syncthreads();
        #pragma unroll 8
        for (int s = 0; s < SCH; s++) {
            float a[4], bf[8];
            #pragma unroll
            for (int i = 0; i < 4; i++) a[i] = sa[ty * 4 + i][s];
            #pragma unroll
            for (int j = 0; j < 8; j++) bf[j] = sb[s][tx * 8 + j];
            #pragma unroll
            for (int i = 0; i < 4; i++)
                #pragma unroll
                for (int j = 0; j < 8; j++)
                    acc[i][j] = fmaf(a[i], bf[j], acc[i][j]);
        }
    }
    #pragma unroll
    for (int i = 0; i < 4; i++) {
        int t = ty * 4 + i;
        #pragma unroll
        for (int j = 0; j < 8; j++) {
            int c = c0 + tx * 8 + j;
            if (c < CV)
                out[(size_t)(t * NB + bb) * OC + VO + c] = acc[i][j];
        }
    }
}

// ---------------- launch ----------------
extern "C" void kernel_launch(void* const* d_in, const int* in_sizes, int n_in,
                              void* d_out, int out_size) {
    const float* hidden = (const float*)d_in[0];
    const float* attn   = (const float*)d_in[1];
    const float* srcm   = (const float*)d_in[2];
    const float* W      = (const float*)d_in[3];
    const float* b      = (const float*)d_in[4];
    const float* Wc     = (const float*)d_in[5];
    const float* bc     = (const float*)d_in[6];
    const int*   pad    = (const int*)d_in[7];
    float* out = (float*)d_out;

    bnorm_kernel<<<1, 256>>>(b);
    row_prep_kernel<<<NR, 256>>>(hidden, Wc, bc);
    gemm_kernel<<<dim3(VO / BN, NR / BM), 256>>>(hidden, W);
    rowred_kernel<<<NR, 256>>>(b);
    softmax_kernel<<<NR, 256>>>(b, pad);
    writeout_kernel<<<NR, 256>>>(b, pad, out);
    copy_kernel<<<dim3((CV + 127) / 128, NB), 256>>>(attn, srcm, out);
}

// round 3
// speedup vs baseline: 1.0021x; 1.0004x over previous
#include <cuda_runtime.h>
#include <math.h>

#define NR 2048      // batch*tlen rows
#define DK 1024      // input dim
#define VO 32000     // vocab
#define SL 512       // slen
#define NB 32        // batch
#define CV 500       // copy vocab
#define OC 32500     // output cols

// ---------------- scratch (device globals; no allocations allowed) ----------
static __device__ float g_Mx[(size_t)NR * VO];   // 262 MB GEMM output
static __device__ float g_xnorm[NR];
static __device__ float g_pcopy[NR];
static __device__ float g_gamma[NR];
static __device__ float g_delta[NR];
static __device__ float g_rowmax[NR];
static __device__ float g_rowsum[NR];
static __device__ float g_y2;                    // ||b||^2

// ---------------- helpers ----------------
__device__ __forceinline__ float block_reduce_sum(float v, float* sbuf) {
    int tid = threadIdx.x;
    sbuf[tid] = v;
    __syncthreads();
    #pragma unroll
    for (int off = 128; off > 0; off >>= 1) {
        if (tid < off) sbuf[tid] += sbuf[tid + off];
        __syncthreads();
    }
    float r = sbuf[0];
    __syncthreads();
    return r;
}

// ---------------- ||b||^2 ----------------
__global__ void __launch_bounds__(256) bnorm_kernel(const float* __restrict__ b) {
    __shared__ float sbuf[256];
    float s = 0.f;
    for (int i = threadIdx.x; i < VO; i += 256) { float v = b[i]; s += v * v; }
    s = block_reduce_sum(s, sbuf);
    if (threadIdx.x == 0) g_y2 = s;
}

// --------- per-row: x_norm, p_copy (V=1 mobius head + sigmoid) ---------
__global__ void __launch_bounds__(256) row_prep_kernel(const float* __restrict__ hidden,
                                                       const float* __restrict__ Wc,
                                                       const float* __restrict__ bcp) {
    __shared__ float s1[256];
    __shared__ float s2[256];
    int row = blockIdx.x;
    const float4* h4 = (const float4*)(hidden + (size_t)row * DK);
    const float4* w4 = (const float4*)Wc;
    int i = threadIdx.x;           // exactly DK/4 = 256 vec elems
    float4 h = h4[i];
    float4 w = w4[i];
    float ss = h.x * h.x + h.y * h.y + h.z * h.z + h.w * h.w;
    float sm = h.x * w.x + h.y * w.y + h.z * w.z + h.w * w.w;
    ss = block_reduce_sum(ss, s1);
    sm = block_reduce_sum(sm, s2);
    if (threadIdx.x == 0) {
        float xn = fmaxf(sqrtf(ss), 1e-15f);
        g_xnorm[row] = xn;
        float art = atanhf(fminf(xn, 1.f - 1e-7f));
        float mn = fmaxf(fabsf(sm), 1e-15f);
        float t1 = tanhf(mn / xn * art) * (sm / mn);
        float bc = *bcp;
        float y2 = bc * bc, x2 = t1 * t1, xy = t1 * bc;
        float num = (1.f + 2.f * xy + y2) * t1 + (1.f - x2) * bc;
        float den = fmaxf(1.f + 2.f * xy + x2 * y2, 1e-15f);
        float u = num / den;
        float au = fmaxf(fabsf(u), 1e-15f);
        if (au > 0.996f) u = u / au * 0.996f;
        g_pcopy[row] = 1.f / (1.f + expf(-u));
    }
}

// ---------------- big GEMM: g_Mx = hidden @ W^T ----------------
#define BM 128
#define BN 128
#define BK 16
__global__ void __launch_bounds__(256) gemm_kernel(const float* __restrict__ A,
                                                   const float* __restrict__ W) {
    __shared__ __align__(16) float As[BK][BM];   // transposed A tile
    __shared__ __align__(16) float Bs[BK][BN];   // transposed W tile
    const int row0 = blockIdx.y * BM;
    const int col0 = blockIdx.x * BN;
    const int tid = threadIdx.x;
    const int tx = tid % 16;       // n dir
    const int ty = tid / 16;       // m dir
    const int lr = tid / 4;        // 0..63
    const int lc = tid % 4;        // float4 slot in BK

    float acc[8][8] = {};

    for (int k0 = 0; k0 < DK; k0 += BK) {
        float4 a0 = *(const float4*)(A + (size_t)(row0 + lr) * DK + k0 + lc * 4);
        float4 a1 = *(const float4*)(A + (size_t)(row0 + lr + 64) * DK + k0 + lc * 4);
        float4 b0 = *(const float4*)(W + (size_t)(col0 + lr) * DK + k0 + lc * 4);
        float4 b1 = *(const float4*)(W + (size_t)(col0 + lr + 64) * DK + k0 + lc * 4);
        __syncthreads();
        As[lc * 4 + 0][lr] = a0.x; As[lc * 4 + 1][lr] = a0.y;
        As[lc * 4 + 2][lr] = a0.z; As[lc * 4 + 3][lr] = a0.w;
        As[lc * 4 + 0][lr + 64] = a1.x; As[lc * 4 + 1][lr + 64] = a1.y;
        As[lc * 4 + 2][lr + 64] = a1.z; As[lc * 4 + 3][lr + 64] = a1.w;
        Bs[lc * 4 + 0][lr] = b0.x; Bs[lc * 4 + 1][lr] = b0.y;
        Bs[lc * 4 + 2][lr] = b0.z; Bs[lc * 4 + 3][lr] = b0.w;
        Bs[lc * 4 + 0][lr + 64] = b1.x; Bs[lc * 4 + 1][lr + 64] = b1.y;
        Bs[lc * 4 + 2][lr + 64] = b1.z; Bs[lc * 4 + 3][lr + 64] = b1.w;
        __syncthreads();
        #pragma unroll
        for (int k = 0; k < BK; k++) {
            float a[8], b[8];
            *(float4*)&a[0] = *(const float4*)&As[k][ty * 8];
            *(float4*)&a[4] = *(const float4*)&As[k][ty * 8 + 4];
            *(float4*)&b[0] = *(const float4*)&Bs[k][tx * 8];
            *(float4*)&b[4] = *(const float4*)&Bs[k][tx * 8 + 4];
            #pragma unroll
            for (int i = 0; i < 8; i++)
                #pragma unroll
                for (int j = 0; j < 8; j++)
                    acc[i][j] = fmaf(a[i], b[j], acc[i][j]);
        }
    }

    #pragma unroll
    for (int i = 0; i < 8; i++) {
        float* cp = g_Mx + (size_t)(row0 + ty * 8 + i) * VO + col0 + tx * 8;
        *(float4*)cp       = *(float4*)&acc[i][0];
        *(float4*)(cp + 4) = *(float4*)&acc[i][4];
    }
}

// ------- per-row reductions over Mx -> gamma, delta (fused mobius chain) -----
__global__ void __launch_bounds__(256) rowred_kernel(const float* __restrict__ b) {
    __shared__ float s1[256];
    __shared__ float s2[256];
    int row = blockIdx.x;
    const float4* mx4 = (const float4*)(g_Mx + (size_t)row * VO);
    const float4* b4 = (const float4*)b;
    float ss = 0.f, db = 0.f;
    for (int i = threadIdx.x; i < VO / 4; i += 256) {
        float4 x = mx4[i];
        float4 y = b4[i];
        ss += x.x * x.x + x.y * x.y + x.z * x.z + x.w * x.w;
        db += x.x * y.x + x.y * y.y + x.z * y.z + x.w * y.w;
    }
    ss = block_reduce_sum(ss, s1);
    db = block_reduce_sum(db, s2);
    if (threadIdx.x == 0) {
        float xn = g_xnorm[row];
        float mxn = fmaxf(sqrtf(ss), 1e-15f);
        float art = atanhf(fminf(xn, 1.f - 1e-7f));
        float t = tanhf(mxn / xn * art);
        float alpha = t / mxn;
        float xy = alpha * db;
        float x2 = t * t;
        float y2 = g_y2;
        float Ac = 1.f + 2.f * xy + y2;
        float Bc = 1.f - x2;
        float den = fmaxf(1.f + 2.f * xy + x2 * y2, 1e-15f);
        float g0 = Ac * alpha / den;
        float d0 = Bc / den;
        // analytic ||logits|| for project()
        float nl2 = (Ac * Ac * t * t + 2.f * Ac * Bc * alpha * db + Bc * Bc * y2) / (den * den);
        float nl = fmaxf(sqrtf(nl2), 1e-15f);
        float sc = (nl > 0.996f) ? (0.996f / nl) : 1.f;
        g_gamma[row] = sc * g0;
        g_delta[row] = sc * d0;
    }
}

// ------- online softmax pass: rowmax + sumexp (pad skipped) -------
__global__ void __launch_bounds__(256) softmax_kernel(const float* __restrict__ b,
                                                      const int* __restrict__ padp) {
    __shared__ float sm[256];
    __shared__ float ssum[256];
    int row = blockIdx.x;
    int pad = *padp;
    const float* mx = g_Mx + (size_t)row * VO;
    float gamma = g_gamma[row], delta = g_delta[row];
    float m = -INFINITY, s = 0.f;
    for (int i = threadIdx.x; i < VO; i += 256) {
        if (i == pad) continue;
        float l = gamma * mx[i] + delta * b[i];
        if (l > m) { s = s * expf(m - l) + 1.f; m = l; }
        else       { s += expf(l - m); }
    }
    int tid = threadIdx.x;
    sm[tid] = m; ssum[tid] = s;
    __syncthreads();
    #pragma unroll
    for (int off = 128; off > 0; off >>= 1) {
        if (tid < off) {
            float m2 = sm[tid + off], s2 = ssum[tid + off];
            float mn = fmaxf(sm[tid], m2);
            ssum[tid] = ssum[tid] * expf(sm[tid] - mn) + s2 * expf(m2 - mn);
            sm[tid] = mn;
        }
        __syncthreads();
    }
    if (tid == 0) { g_rowmax[row] = sm[0]; g_rowsum[row] = ssum[0]; }
}

// ------- write out_prob = softmax * (1 - p_copy) -------
__global__ void __launch_bounds__(256) writeout_kernel(const float* __restrict__ b,
                                                       const int* __restrict__ padp,
                                                       float* __restrict__ out) {
    int row = blockIdx.x;
    int pad = *padp;
    const float4* mx4 = (const float4*)(g_Mx + (size_t)row * VO);
    const float4* b4 = (const float4*)b;
    float gamma = g_gamma[row], delta = g_delta[row];
    float m = g_rowmax[row];
    float inv = (1.f - g_pcopy[row]) / g_rowsum[row];
    float4* o4 = (float4*)(out + (size_t)row * OC);
    for (int i = threadIdx.x; i < VO / 4; i += 256) {
        float4 x = mx4[i];
        float4 bb = b4[i];
        float4 r;
        r.x = expf(gamma * x.x + delta * bb.x - m) * inv;
        r.y = expf(gamma * x.y + delta * bb.y - m) * inv;
        r.z = expf(gamma * x.z + delta * bb.z - m) * inv;
        r.w = expf(gamma * x.w + delta * bb.w - m) * inv;
        int base = i * 4;
        if (pad >= base && pad < base + 4) ((float*)&r)[pad - base] = 0.f;
        o4[i] = r;
    }
}

// ------- copy branch: per-batch (64x512)@(512x500) small GEMM -------
#define SCH 32
__global__ void __launch_bounds__(256) copy_kernel(const float* __restrict__ attn,
                                                   const float* __restrict__ src,
                                                   float* __restrict__ out) {
    __shared__ float sa[64][SCH + 1];   // [t][s], padded
    __shared__ float sb[SCH][128];      // [s][c]
    __shared__ float spc[64];
    const int bb = blockIdx.y;
    const int c0 = blockIdx.x * 128;
    const int tid = threadIdx.x;
    const int tx = tid % 16;            // c groups of 8
    const int ty = tid / 16;            // t groups of 4

    if (tid < 64) spc[tid] = g_pcopy[tid * NB + bb];

    float acc[4][8] = {};
    for (int s0 = 0; s0 < SL; s0 += SCH) {
        __syncthreads();
        // load attn tile * p_copy : 64 x 32
        for (int i = tid; i < 64 * (SCH / 4); i += 256) {
            int t = i / (SCH / 4);
            int sv = i % (SCH / 4);
            float4 v = *(const float4*)(attn + (size_t)(t * NB + bb) * SL + s0 + sv * 4);
            float pc = spc[t];
            sa[t][sv * 4 + 0] = v.x * pc;
            sa[t][sv * 4 + 1] = v.y * pc;
            sa[t][sv * 4 + 2] = v.z * pc;
            sa[t][sv * 4 + 3] = v.w * pc;
        }
        // load src_map tile : 32 x 128 (guarded at c>=500)
        for (int i = tid; i < SCH * 128; i += 256) {
            int s = i / 128;
            int c = i % 128;
            int cg = c0 + c;
            sb[s][c] = (cg < CV) ? src[(size_t)(s0 + s) * (NB * CV) + bb * CV + cg] : 0.f;
        }
        __syncthreads();
        #pragma unroll 8
        for (int s = 0; s < SCH; s++) {
            float a[4], bf[8];
            #pragma unroll
            for (int i = 0; i < 4; i++) a[i] = sa[ty * 4 + i][s];
            #pragma unroll
            for (int j = 0; j < 8; j++) bf[j] = sb[s][tx * 8 + j];
            #pragma unroll
            for (int i = 0; i < 4; i++)
                #pragma unroll
                for (int j = 0; j < 8; j++)
                    acc[i][j] = fmaf(a[i], bf[j], acc[i][j]);
        }
    }
    #pragma unroll
    for (int i = 0; i < 4; i++) {
        int t = ty * 4 + i;
        #pragma unroll
        for (int j = 0; j < 8; j++) {
            int c = c0 + tx * 8 + j;
            if (c < CV)
                out[(size_t)(t * NB + bb) * OC + VO + c] = acc[i][j];
        }
    }
}

// ---------------- launch ----------------
extern "C" void kernel_launch(void* const* d_in, const int* in_sizes, int n_in,
                              void* d_out, int out_size) {
    const float* hidden = (const float*)d_in[0];
    const float* attn   = (const float*)d_in[1];
    const float* srcm   = (const float*)d_in[2];
    const float* W      = (const float*)d_in[3];
    const float* b      = (const float*)d_in[4];
    const float* Wc     = (const float*)d_in[5];
    const float* bc     = (const float*)d_in[6];
    const int*   pad    = (const int*)d_in[7];
    float* out = (float*)d_out;

    bnorm_kernel<<<1, 256>>>(b);
    row_prep_kernel<<<NR, 256>>>(hidden, Wc, bc);
    gemm_kernel<<<dim3(VO / BN, NR / BM), 256>>>(hidden, W);
    rowred_kernel<<<NR, 256>>>(b);
    softmax_kernel<<<NR, 256>>>(b, pad);
    writeout_kernel<<<NR, 256>>>(b, pad, out);
    copy_kernel<<<dim3((CV + 127) / 128, NB), 256>>>(attn, srcm, out);
}

// round 5
// speedup vs baseline: 4.9552x; 4.9447x over previous
#include <cuda_runtime.h>
#include <cuda_bf16.h>
#include <math.h>
#include <stdint.h>

#define NR 2048      // batch*tlen rows
#define DK 1024      // input dim
#define VO 32000     // vocab
#define SL 512       // slen
#define NB 32        // batch
#define CV 500       // copy vocab
#define OC 32500     // output cols

// ---------------- scratch (device globals) ----------------
static __device__ float g_Mx[(size_t)NR * VO];                  // 262 MB logits (pre-affine)
static __device__ __nv_bfloat16 g_hid_bf[(size_t)NR * DK];      // 4 MB
static __device__ __nv_bfloat16 g_W_bf[(size_t)VO * DK];        // 65.5 MB
static __device__ float g_xnorm[NR];
static __device__ float g_pcopy[NR];
static __device__ float g_gamma[NR];
static __device__ float g_delta[NR];
static __device__ float g_rowmax[NR];
static __device__ float g_rowsum[NR];
static __device__ float g_ss[NR];
static __device__ float g_db[NR];
static __device__ float g_y2;

// ---------------- helpers ----------------
__device__ __forceinline__ uint32_t smem_u32(const void* p) {
    uint32_t a;
    asm("{ .reg .u64 t; cvta.to.shared.u64 t, %1; cvt.u32.u64 %0, t; }" : "=r"(a) : "l"(p));
    return a;
}
__device__ __forceinline__ void cp16(uint32_t saddr, const void* g) {
    asm volatile("cp.async.cg.shared.global [%0], [%1], 16;" :: "r"(saddr), "l"(g));
}
__device__ __forceinline__ float block_reduce_sum(float v, float* sbuf) {
    int tid = threadIdx.x;
    sbuf[tid] = v;
    __syncthreads();
    #pragma unroll
    for (int off = 128; off > 0; off >>= 1) {
        if (tid < off) sbuf[tid] += sbuf[tid + off];
        __syncthreads();
    }
    float r = sbuf[0];
    __syncthreads();
    return r;
}

// ---------------- dtype conversion ----------------
__global__ void __launch_bounds__(256) conv_bf16_kernel(const float* __restrict__ src,
                                                        __nv_bfloat16* __restrict__ dst,
                                                        int n4) {
    int i = blockIdx.x * 256 + threadIdx.x;
    if (i < n4) {
        float4 v = ((const float4*)src)[i];
        __nv_bfloat162 lo = __floats2bfloat162_rn(v.x, v.y);
        __nv_bfloat162 hi = __floats2bfloat162_rn(v.z, v.w);
        ((__nv_bfloat162*)dst)[2 * i]     = lo;
        ((__nv_bfloat162*)dst)[2 * i + 1] = hi;
    }
}

// ---------------- ||b||^2 ----------------
__global__ void __launch_bounds__(256) bnorm_kernel(const float* __restrict__ b) {
    __shared__ float sbuf[256];
    float s = 0.f;
    for (int i = threadIdx.x; i < VO; i += 256) { float v = b[i]; s += v * v; }
    s = block_reduce_sum(s, sbuf);
    if (threadIdx.x == 0) g_y2 = s;
}

// --------- per-row: x_norm, p_copy + zero row accumulators ---------
__global__ void __launch_bounds__(256) row_prep_kernel(const float* __restrict__ hidden,
                                                       const float* __restrict__ Wc,
                                                       const float* __restrict__ bcp) {
    __shared__ float s1[256];
    __shared__ float s2[256];
    int row = blockIdx.x;
    const float4* h4 = (const float4*)(hidden + (size_t)row * DK);
    const float4* w4 = (const float4*)Wc;
    int i = threadIdx.x;
    float4 h = h4[i];
    float4 w = w4[i];
    float ss = h.x * h.x + h.y * h.y + h.z * h.z + h.w * h.w;
    float sm = h.x * w.x + h.y * w.y + h.z * w.z + h.w * w.w;
    ss = block_reduce_sum(ss, s1);
    sm = block_reduce_sum(sm, s2);
    if (threadIdx.x == 0) {
        g_ss[row] = 0.f;
        g_db[row] = 0.f;
        float xn = fmaxf(sqrtf(ss), 1e-15f);
        g_xnorm[row] = xn;
        float art = atanhf(fminf(xn, 1.f - 1e-7f));
        float mn = fmaxf(fabsf(sm), 1e-15f);
        float t1 = tanhf(mn / xn * art) * (sm / mn);
        float bc = *bcp;
        float y2 = bc * bc, x2 = t1 * t1, xy = t1 * bc;
        float num = (1.f + 2.f * xy + y2) * t1 + (1.f - x2) * bc;
        float den = fmaxf(1.f + 2.f * xy + x2 * y2, 1e-15f);
        float u = num / den;
        float au = fmaxf(fabsf(u), 1e-15f);
        if (au > 0.996f) u = u / au * 0.996f;
        g_pcopy[row] = 1.f / (1.f + expf(-u));
    }
}

// ================ bf16 mma.sync GEMM: g_Mx = hidden @ W^T (+ fused reductions) ===
// CTA tile 128x128, BK=64, double-buffered cp.async, 8 warps (2 m x 4 n), warp 64x32.
#define BM 128
#define BN 128
#define BK 64
#define NSTG (DK / BK)          // 16
#define STAGE_BYTES 32768       // A 16KB + B 16KB
#define SMEM_GEMM (2 * STAGE_BYTES)

__device__ __forceinline__ uint32_t sw128(uint32_t off) {
    return off ^ ((off >> 3) & 0x70);
}

__global__ void __launch_bounds__(256) gemm_mma_kernel(const float* __restrict__ bvec) {
    extern __shared__ char smem[];
    const uint32_t sb = smem_u32(smem);
    const int tid = threadIdx.x;
    const int wid = tid >> 5;
    const int lane = tid & 31;
    const int warp_m = wid & 1;         // 0..1  (64-row block)
    const int warp_n = wid >> 1;        // 0..3  (32-col block)
    const int row0 = blockIdx.y * BM;
    const int col0 = blockIdx.x * BN;

    // per-thread load coords (4 x 16B chunks for A, 4 for B per stage)
    const int lr = tid >> 3;            // 0..31 base row
    const int lk = tid & 7;             // 16B k-group

    float acc[4][4][4];                  // [mf][nf][reg]
    #pragma unroll
    for (int a = 0; a < 4; a++)
        #pragma unroll
        for (int b = 0; b < 4; b++)
            #pragma unroll
            for (int c = 0; c < 4; c++) acc[a][b][c] = 0.f;

    // ---- prologue: load stage 0 ----
    {
        const uint32_t abase = sb, bbase = sb + 16384;
        #pragma unroll
        for (int it = 0; it < 4; it++) {
            int r = lr + it * 32;
            uint32_t off = sw128(r * 128 + lk * 16);
            cp16(abase + off, g_hid_bf + (size_t)(row0 + r) * DK + lk * 8);
            cp16(bbase + off, g_W_bf + (size_t)(col0 + r) * DK + lk * 8);
        }
        asm volatile("cp.async.commit_group;" ::: "memory");
        asm volatile("cp.async.wait_group 0;" ::: "memory");
    }
    __syncthreads();

    for (int ks = 0; ks < NSTG; ks++) {
        // issue loads for next stage into the other buffer
        if (ks + 1 < NSTG) {
            const uint32_t nb = sb + ((ks + 1) & 1) * STAGE_BYTES;
            const int k0 = (ks + 1) * BK;
            #pragma unroll
            for (int it = 0; it < 4; it++) {
                int r = lr + it * 32;
                uint32_t off = sw128(r * 128 + lk * 16);
                cp16(nb + off, g_hid_bf + (size_t)(row0 + r) * DK + k0 + lk * 8);
                cp16(nb + 16384 + off, g_W_bf + (size_t)(col0 + r) * DK + k0 + lk * 8);
            }
            asm volatile("cp.async.commit_group;" ::: "memory");
        }

        // compute on current stage
        const uint32_t abase = sb + (ks & 1) * STAGE_BYTES;
        const uint32_t bbase = abase + 16384;
        #pragma unroll
        for (int kk = 0; kk < 4; kk++) {        // 4 x k16
            uint32_t afr[4][4];
            uint32_t bfr[4][2];
            #pragma unroll
            for (int mf = 0; mf < 4; mf++) {
                int r = warp_m * 64 + mf * 16 + (lane & 15);
                uint32_t off = sw128(r * 128 + kk * 32 + ((lane >> 4) & 1) * 16);
                asm volatile("ldmatrix.sync.aligned.m8n8.x4.shared.b16 {%0,%1,%2,%3}, [%4];"
                             : "=r"(afr[mf][0]), "=r"(afr[mf][1]),
                               "=r"(afr[mf][2]), "=r"(afr[mf][3])
                             : "r"(abase + off));
            }
            #pragma unroll
            for (int nf = 0; nf < 4; nf++) {
                int r = warp_n * 32 + nf * 8 + (lane & 7);
                uint32_t off = sw128(r * 128 + kk * 32 + ((lane >> 3) & 1) * 16);
                asm volatile("ldmatrix.sync.aligned.m8n8.x2.shared.b16 {%0,%1}, [%2];"
                             : "=r"(bfr[nf][0]), "=r"(bfr[nf][1])
                             : "r"(bbase + off));
            }
            #pragma unroll
            for (int mf = 0; mf < 4; mf++)
                #pragma unroll
                for (int nf = 0; nf < 4; nf++) {
                    asm volatile(
                        "mma.sync.aligned.m16n8k16.row.col.f32.bf16.bf16.f32 "
                        "{%0,%1,%2,%3}, {%4,%5,%6,%7}, {%8,%9}, {%0,%1,%2,%3};"
                        : "+f"(acc[mf][nf][0]), "+f"(acc[mf][nf][1]),
                          "+f"(acc[mf][nf][2]), "+f"(acc[mf][nf][3])
                        : "r"(afr[mf][0]), "r"(afr[mf][1]),
                          "r"(afr[mf][2]), "r"(afr[mf][3]),
                          "r"(bfr[nf][0]), "r"(bfr[nf][1]));
                }
        }
        if (ks + 1 < NSTG)
            asm volatile("cp.async.wait_group 0;" ::: "memory");
        __syncthreads();
    }

    // ---- epilogue: write Mx fp32 + fused ss/db row reductions ----
    float bb[4][2];
    #pragma unroll
    for (int nf = 0; nf < 4; nf++) {
        int c = col0 + warp_n * 32 + nf * 8 + (lane & 3) * 2;
        float2 v = *(const float2*)(bvec + c);
        bb[nf][0] = v.x; bb[nf][1] = v.y;
    }
    float ssr[4][2], dbr[4][2];
    #pragma unroll
    for (int mf = 0; mf < 4; mf++) {
        #pragma unroll
        for (int hf = 0; hf < 2; hf++) {
            int row = row0 + warp_m * 64 + mf * 16 + (lane >> 2) + hf * 8;
            float* orow = g_Mx + (size_t)row * VO + col0 + warp_n * 32 + (lane & 3) * 2;
            float ss = 0.f, db = 0.f;
            #pragma unroll
            for (int nf = 0; nf < 4; nf++) {
                float c0 = acc[mf][nf][hf * 2];
                float c1 = acc[mf][nf][hf * 2 + 1];
                ss += c0 * c0 + c1 * c1;
                db += c0 * bb[nf][0] + c1 * bb[nf][1];
                *(float2*)(orow + nf * 8) = make_float2(c0, c1);
            }
            ssr[mf][hf] = ss; dbr[mf][hf] = db;
        }
    }
    // reduce across the 4 lanes of each quad (same rows, different cols)
    #pragma unroll
    for (int mf = 0; mf < 4; mf++)
        #pragma unroll
        for (int hf = 0; hf < 2; hf++) {
            float ss = ssr[mf][hf], db = dbr[mf][hf];
            ss += __shfl_xor_sync(0xffffffff, ss, 1);
            ss += __shfl_xor_sync(0xffffffff, ss, 2);
            db += __shfl_xor_sync(0xffffffff, db, 1);
            db += __shfl_xor_sync(0xffffffff, db, 2);
            if ((lane & 3) == 0) {
                int row = row0 + warp_m * 64 + mf * 16 + (lane >> 2) + hf * 8;
                atomicAdd(&g_ss[row], ss);
                atomicAdd(&g_db[row], db);
            }
        }
}

// ------- per-row scalar chain: gamma, delta from fused reductions -------
__global__ void __launch_bounds__(256) scalar_kernel() {
    int row = blockIdx.x * 256 + threadIdx.x;
    if (row >= NR) return;
    float ss = g_ss[row];
    float db = g_db[row];
    float xn = g_xnorm[row];
    float mxn = fmaxf(sqrtf(ss), 1e-15f);
    float art = atanhf(fminf(xn, 1.f - 1e-7f));
    float t = tanhf(mxn / xn * art);
    float alpha = t / mxn;
    float xy = alpha * db;
    float x2 = t * t;
    float y2 = g_y2;
    float Ac = 1.f + 2.f * xy + y2;
    float Bc = 1.f - x2;
    float den = fmaxf(1.f + 2.f * xy + x2 * y2, 1e-15f);
    float g0 = Ac * alpha / den;
    float d0 = Bc / den;
    float nl2 = (Ac * Ac * t * t + 2.f * Ac * Bc * alpha * db + Bc * Bc * y2) / (den * den);
    float nl = fmaxf(sqrtf(nl2), 1e-15f);
    float sc = (nl > 0.996f) ? (0.996f / nl) : 1.f;
    g_gamma[row] = sc * g0;
    g_delta[row] = sc * d0;
}

// ------- online softmax stats: rowmax + sumexp (pad skipped) -------
__global__ void __launch_bounds__(256) softmax_kernel(const float* __restrict__ b,
                                                      const int* __restrict__ padp) {
    __shared__ float sm[256];
    __shared__ float ssum[256];
    int row = blockIdx.x;
    int pad = *padp;
    const float4* mx4 = (const float4*)(g_Mx + (size_t)row * VO);
    const float4* b4 = (const float4*)b;
    float gamma = g_gamma[row], delta = g_delta[row];
    float m = -INFINITY, s = 0.f;
    for (int i = threadIdx.x; i < VO / 4; i += 256) {
        float4 x = mx4[i];
        float4 bbv = b4[i];
        float l[4];
        l[0] = gamma * x.x + delta * bbv.x;
        l[1] = gamma * x.y + delta * bbv.y;
        l[2] = gamma * x.z + delta * bbv.z;
        l[3] = gamma * x.w + delta * bbv.w;
        int base = i * 4;
        if ((unsigned)(pad - base) < 4u) l[pad - base] = -INFINITY;
        #pragma unroll
        for (int j = 0; j < 4; j++) {
            float lv = l[j];
            if (lv > m) { s = s * expf(m - lv) + 1.f; m = lv; }
            else        { s += expf(lv - m); }
        }
    }
    int tid = threadIdx.x;
    sm[tid] = m; ssum[tid] = s;
    __syncthreads();
    #pragma unroll
    for (int off = 128; off > 0; off >>= 1) {
        if (tid < off) {
            float m2 = sm[tid + off], s2 = ssum[tid + off];
            float mn = fmaxf(sm[tid], m2);
            ssum[tid] = ssum[tid] * expf(sm[tid] - mn) + s2 * expf(m2 - mn);
            sm[tid] = mn;
        }
        __syncthreads();
    }
    if (tid == 0) { g_rowmax[row] = sm[0]; g_rowsum[row] = ssum[0]; }
}

// ------- write out_prob = softmax * (1 - p_copy) -------
__global__ void __launch_bounds__(256) writeout_kernel(const float* __restrict__ b,
                                                       const int* __restrict__ padp,
                                                       float* __restrict__ out) {
    int row = blockIdx.x;
    int pad = *padp;
    const float4* mx4 = (const float4*)(g_Mx + (size_t)row * VO);
    const float4* b4 = (const float4*)b;
    float gamma = g_gamma[row], delta = g_delta[row];
    float m = g_rowmax[row];
    float inv = (1.f - g_pcopy[row]) / g_rowsum[row];
    float4* o4 = (float4*)(out + (size_t)row * OC);
    for (int i = threadIdx.x; i < VO / 4; i += 256) {
        float4 x = mx4[i];
        float4 bbv = b4[i];
        float4 r;
        r.x = expf(gamma * x.x + delta * bbv.x - m) * inv;
        r.y = expf(gamma * x.y + delta * bbv.y - m) * inv;
        r.z = expf(gamma * x.z + delta * bbv.z - m) * inv;
        r.w = expf(gamma * x.w + delta * bbv.w - m) * inv;
        int base = i * 4;
        if ((unsigned)(pad - base) < 4u) ((float*)&r)[pad - base] = 0.f;
        o4[i] = r;
    }
}

// ------- copy branch: per-batch (64x512)@(512x500) small GEMM -------
#define SCH 32
__global__ void __launch_bounds__(256) copy_kernel(const float* __restrict__ attn,
                                                   const float* __restrict__ src,
                                                   float* __restrict__ out) {
    __shared__ float sa[64][SCH + 1];
    __shared__ float sbuf[SCH][128];
    __shared__ float spc[64];
    const int bb = blockIdx.y;
    const int c0 = blockIdx.x * 128;
    const int tid = threadIdx.x;
    const int tx = tid % 16;
    const int ty = tid / 16;

    if (tid < 64) spc[tid] = g_pcopy[tid * NB + bb];

    float acc[4][8] = {};
    for (int s0 = 0; s0 < SL; s0 += SCH) {
        __syncthreads();
        for (int i = tid; i < 64 * (SCH / 4); i += 256) {
            int t = i / (SCH / 4);
            int sv = i % (SCH / 4);
            float4 v = *(const float4*)(attn + (size_t)(t * NB + bb) * SL + s0 + sv * 4);
            float pc = spc[t];
            sa[t][sv * 4 + 0] = v.x * pc;
            sa[t][sv * 4 + 1] = v.y * pc;
            sa[t][sv * 4 + 2] = v.z * pc;
            sa[t][sv * 4 + 3] = v.w * pc;
        }
        for (int i = tid; i < SCH * 128; i += 256) {
            int s = i / 128;
            int c = i % 128;
            int cg = c0 + c;
            sbuf[s][c] = (cg < CV) ? src[(size_t)(s0 + s) * (NB * CV) + bb * CV + cg] : 0.f;
        }
        __syncthreads();
        #pragma unroll 8
        for (int s = 0; s < SCH; s++) {
            float a[4], bf[8];
            #pragma unroll
            for (int i = 0; i < 4; i++) a[i] = sa[ty * 4 + i][s];
            #pragma unroll
            for (int j = 0; j < 8; j++) bf[j] = sbuf[s][tx * 8 + j];
            #pragma unroll
            for (int i = 0; i < 4; i++)
                #pragma unroll
                for (int j = 0; j < 8; j++)
                    acc[i][j] = fmaf(a[i], bf[j], acc[i][j]);
        }
    }
    #pragma unroll
    for (int i = 0; i < 4; i++) {
        int t = ty * 4 + i;
        #pragma unroll
        for (int j = 0; j < 8; j++) {
            int c = c0 + tx * 8 + j;
            if (c < CV)
                out[(size_t)(t * NB + bb) * OC + VO + c] = acc[i][j];
        }
    }
}

// ---------------- launch ----------------
extern "C" void kernel_launch(void* const* d_in, const int* in_sizes, int n_in,
                              void* d_out, int out_size) {
    const float* hidden = (const float*)d_in[0];
    const float* attn   = (const float*)d_in[1];
    const float* srcm   = (const float*)d_in[2];
    const float* W      = (const float*)d_in[3];
    const float* b      = (const float*)d_in[4];
    const float* Wc     = (const float*)d_in[5];
    const float* bc     = (const float*)d_in[6];
    const int*   pad    = (const int*)d_in[7];
    float* out = (float*)d_out;

    cudaFuncSetAttribute(gemm_mma_kernel,
                         cudaFuncAttributeMaxDynamicSharedMemorySize, SMEM_GEMM);

    __nv_bfloat16* hid_bf;
    __nv_bfloat16* W_bf;
    cudaGetSymbolAddress((void**)&hid_bf, g_hid_bf);
    cudaGetSymbolAddress((void**)&W_bf, g_W_bf);

    conv_bf16_kernel<<<(NR * DK / 4 + 255) / 256, 256>>>(hidden, hid_bf, NR * DK / 4);
    conv_bf16_kernel<<<(VO * DK / 4 + 255) / 256, 256>>>(W, W_bf, VO * DK / 4);
    bnorm_kernel<<<1, 256>>>(b);
    row_prep_kernel<<<NR, 256>>>(hidden, Wc, bc);
    gemm_mma_kernel<<<dim3(VO / BN, NR / BM), 256, SMEM_GEMM>>>(b);
    scalar_kernel<<<NR / 256, 256>>>();
    softmax_kernel<<<NR, 256>>>(b, pad);
    writeout_kernel<<<NR, 256>>>(b, pad, out);
    copy_kernel<<<dim3((CV + 127) / 128, NB), 256>>>(attn, srcm, out);
}

// round 6
// speedup vs baseline: 5.6240x; 1.1350x over previous
#include <cuda_runtime.h>
#include <cuda_bf16.h>
#include <math.h>
#include <stdint.h>

#define NR 2048      // batch*tlen rows
#define DK 1024      // input dim
#define VO 32000     // vocab
#define SL 512       // slen
#define NB 32        // batch
#define CV 500       // copy vocab
#define OC 32500     // output cols

// ---------------- scratch (device globals) ----------------
static __device__ __nv_bfloat16 g_Mx[(size_t)NR * VO];          // 131 MB logits (pre-affine)
static __device__ __nv_bfloat16 g_hid_bf[(size_t)NR * DK];      // 4 MB
static __device__ __nv_bfloat16 g_W_bf[(size_t)VO * DK];        // 65.5 MB
static __device__ float g_xnorm[NR];
static __device__ float g_pcopy[NR];
static __device__ float g_ss[NR];
static __device__ float g_db[NR];
static __device__ float g_y2;

// ---------------- helpers ----------------
__device__ __forceinline__ uint32_t smem_u32(const void* p) {
    uint32_t a;
    asm("{ .reg .u64 t; cvta.to.shared.u64 t, %1; cvt.u32.u64 %0, t; }" : "=r"(a) : "l"(p));
    return a;
}
__device__ __forceinline__ void cp16(uint32_t saddr, const void* g) {
    asm volatile("cp.async.cg.shared.global [%0], [%1], 16;" :: "r"(saddr), "l"(g));
}
__device__ __forceinline__ float block_reduce_sum(float v, float* sbuf) {
    int tid = threadIdx.x;
    sbuf[tid] = v;
    __syncthreads();
    #pragma unroll
    for (int off = 128; off > 0; off >>= 1) {
        if (tid < off) sbuf[tid] += sbuf[tid + off];
        __syncthreads();
    }
    float r = sbuf[0];
    __syncthreads();
    return r;
}

// ---------------- dtype conversion ----------------
__global__ void __launch_bounds__(256) conv_bf16_kernel(const float* __restrict__ src,
                                                        __nv_bfloat16* __restrict__ dst,
                                                        int n4) {
    int i = blockIdx.x * 256 + threadIdx.x;
    if (i < n4) {
        float4 v = ((const float4*)src)[i];
        __nv_bfloat162 lo = __floats2bfloat162_rn(v.x, v.y);
        __nv_bfloat162 hi = __floats2bfloat162_rn(v.z, v.w);
        ((__nv_bfloat162*)dst)[2 * i]     = lo;
        ((__nv_bfloat162*)dst)[2 * i + 1] = hi;
    }
}

// ---------------- ||b||^2 ----------------
__global__ void __launch_bounds__(256) bnorm_kernel(const float* __restrict__ b) {
    __shared__ float sbuf[256];
    float s = 0.f;
    for (int i = threadIdx.x; i < VO; i += 256) { float v = b[i]; s += v * v; }
    s = block_reduce_sum(s, sbuf);
    if (threadIdx.x == 0) g_y2 = s;
}

// --------- per-row: x_norm, p_copy + zero row accumulators ---------
__global__ void __launch_bounds__(256) row_prep_kernel(const float* __restrict__ hidden,
                                                       const float* __restrict__ Wc,
                                                       const float* __restrict__ bcp) {
    __shared__ float s1[256];
    __shared__ float s2[256];
    int row = blockIdx.x;
    const float4* h4 = (const float4*)(hidden + (size_t)row * DK);
    const float4* w4 = (const float4*)Wc;
    int i = threadIdx.x;
    float4 h = h4[i];
    float4 w = w4[i];
    float ss = h.x * h.x + h.y * h.y + h.z * h.z + h.w * h.w;
    float sm = h.x * w.x + h.y * w.y + h.z * w.z + h.w * w.w;
    ss = block_reduce_sum(ss, s1);
    sm = block_reduce_sum(sm, s2);
    if (threadIdx.x == 0) {
        g_ss[row] = 0.f;
        g_db[row] = 0.f;
        float xn = fmaxf(sqrtf(ss), 1e-15f);
        g_xnorm[row] = xn;
        float art = atanhf(fminf(xn, 1.f - 1e-7f));
        float mn = fmaxf(fabsf(sm), 1e-15f);
        float t1 = tanhf(mn / xn * art) * (sm / mn);
        float bc = *bcp;
        float y2 = bc * bc, x2 = t1 * t1, xy = t1 * bc;
        float num = (1.f + 2.f * xy + y2) * t1 + (1.f - x2) * bc;
        float den = fmaxf(1.f + 2.f * xy + x2 * y2, 1e-15f);
        float u = num / den;
        float au = fmaxf(fabsf(u), 1e-15f);
        if (au > 0.996f) u = u / au * 0.996f;
        g_pcopy[row] = 1.f / (1.f + expf(-u));
    }
}

// ================ bf16 mma.sync GEMM: g_Mx = hidden @ W^T (+ fused reductions) ===
#define BM 128
#define BN 128
#define BK 64
#define NSTG (DK / BK)          // 16
#define STAGE_BYTES 32768
#define SMEM_GEMM (2 * STAGE_BYTES)

__device__ __forceinline__ uint32_t sw128(uint32_t off) {
    return off ^ ((off >> 3) & 0x70);
}

__global__ void __launch_bounds__(256) gemm_mma_kernel(const float* __restrict__ bvec) {
    extern __shared__ char smem[];
    const uint32_t sb = smem_u32(smem);
    const int tid = threadIdx.x;
    const int wid = tid >> 5;
    const int lane = tid & 31;
    const int warp_m = wid & 1;
    const int warp_n = wid >> 1;
    const int row0 = blockIdx.y * BM;
    const int col0 = blockIdx.x * BN;

    const int lr = tid >> 3;
    const int lk = tid & 7;

    float acc[4][4][4];
    #pragma unroll
    for (int a = 0; a < 4; a++)
        #pragma unroll
        for (int b = 0; b < 4; b++)
            #pragma unroll
            for (int c = 0; c < 4; c++) acc[a][b][c] = 0.f;

    {
        const uint32_t abase = sb, bbase = sb + 16384;
        #pragma unroll
        for (int it = 0; it < 4; it++) {
            int r = lr + it * 32;
            uint32_t off = sw128(r * 128 + lk * 16);
            cp16(abase + off, g_hid_bf + (size_t)(row0 + r) * DK + lk * 8);
            cp16(bbase + off, g_W_bf + (size_t)(col0 + r) * DK + lk * 8);
        }
        asm volatile("cp.async.commit_group;" ::: "memory");
        asm volatile("cp.async.wait_group 0;" ::: "memory");
    }
    __syncthreads();

    for (int ks = 0; ks < NSTG; ks++) {
        if (ks + 1 < NSTG) {
            const uint32_t nb = sb + ((ks + 1) & 1) * STAGE_BYTES;
            const int k0 = (ks + 1) * BK;
            #pragma unroll
            for (int it = 0; it < 4; it++) {
                int r = lr + it * 32;
                uint32_t off = sw128(r * 128 + lk * 16);
                cp16(nb + off, g_hid_bf + (size_t)(row0 + r) * DK + k0 + lk * 8);
                cp16(nb + 16384 + off, g_W_bf + (size_t)(col0 + r) * DK + k0 + lk * 8);
            }
            asm volatile("cp.async.commit_group;" ::: "memory");
        }

        const uint32_t abase = sb + (ks & 1) * STAGE_BYTES;
        const uint32_t bbase = abase + 16384;
        #pragma unroll
        for (int kk = 0; kk < 4; kk++) {
            uint32_t afr[4][4];
            uint32_t bfr[4][2];
            #pragma unroll
            for (int mf = 0; mf < 4; mf++) {
                int r = warp_m * 64 + mf * 16 + (lane & 15);
                uint32_t off = sw128(r * 128 + kk * 32 + ((lane >> 4) & 1) * 16);
                asm volatile("ldmatrix.sync.aligned.m8n8.x4.shared.b16 {%0,%1,%2,%3}, [%4];"
                             : "=r"(afr[mf][0]), "=r"(afr[mf][1]),
                               "=r"(afr[mf][2]), "=r"(afr[mf][3])
                             : "r"(abase + off));
            }
            // B fragments: one ldmatrix.x4 covers two n8 fragments (both k-halves)
            #pragma unroll
            for (int nh = 0; nh < 2; nh++) {
                int r = warp_n * 32 + nh * 16 + ((lane >> 4) & 1) * 8 + (lane & 7);
                uint32_t off = sw128(r * 128 + kk * 32 + ((lane >> 3) & 1) * 16);
                asm volatile("ldmatrix.sync.aligned.m8n8.x4.shared.b16 {%0,%1,%2,%3}, [%4];"
                             : "=r"(bfr[nh * 2][0]), "=r"(bfr[nh * 2][1]),
                               "=r"(bfr[nh * 2 + 1][0]), "=r"(bfr[nh * 2 + 1][1])
                             : "r"(bbase + off));
            }
            #pragma unroll
            for (int mf = 0; mf < 4; mf++)
                #pragma unroll
                for (int nf = 0; nf < 4; nf++) {
                    asm volatile(
                        "mma.sync.aligned.m16n8k16.row.col.f32.bf16.bf16.f32 "
                        "{%0,%1,%2,%3}, {%4,%5,%6,%7}, {%8,%9}, {%0,%1,%2,%3};"
                        : "+f"(acc[mf][nf][0]), "+f"(acc[mf][nf][1]),
                          "+f"(acc[mf][nf][2]), "+f"(acc[mf][nf][3])
                        : "r"(afr[mf][0]), "r"(afr[mf][1]),
                          "r"(afr[mf][2]), "r"(afr[mf][3]),
                          "r"(bfr[nf][0]), "r"(bfr[nf][1]));
                }
        }
        if (ks + 1 < NSTG)
            asm volatile("cp.async.wait_group 0;" ::: "memory");
        __syncthreads();
    }

    // ---- epilogue: write Mx bf16 + fused ss/db row reductions (fp32 accs) ----
    float bb[4][2];
    #pragma unroll
    for (int nf = 0; nf < 4; nf++) {
        int c = col0 + warp_n * 32 + nf * 8 + (lane & 3) * 2;
        float2 v = *(const float2*)(bvec + c);
        bb[nf][0] = v.x; bb[nf][1] = v.y;
    }
    #pragma unroll
    for (int mf = 0; mf < 4; mf++) {
        #pragma unroll
        for (int hf = 0; hf < 2; hf++) {
            int row = row0 + warp_m * 64 + mf * 16 + (lane >> 2) + hf * 8;
            __nv_bfloat16* orow = g_Mx + (size_t)row * VO + col0 + warp_n * 32 + (lane & 3) * 2;
            float ss = 0.f, db = 0.f;
            #pragma unroll
            for (int nf = 0; nf < 4; nf++) {
                float c0 = acc[mf][nf][hf * 2];
                float c1 = acc[mf][nf][hf * 2 + 1];
                ss += c0 * c0 + c1 * c1;
                db += c0 * bb[nf][0] + c1 * bb[nf][1];
                *(__nv_bfloat162*)(orow + nf * 8) = __floats2bfloat162_rn(c0, c1);
            }
            ss += __shfl_xor_sync(0xffffffff, ss, 1);
            ss += __shfl_xor_sync(0xffffffff, ss, 2);
            db += __shfl_xor_sync(0xffffffff, db, 1);
            db += __shfl_xor_sync(0xffffffff, db, 2);
            if ((lane & 3) == 0) {
                atomicAdd(&g_ss[row], ss);
                atomicAdd(&g_db[row], db);
            }
        }
    }
}

// ====== fused output: scalar chain + exact softmax (no max needed: |l|<=0.996) ======
// one block per row; Mx row cached in 64KB dynamic smem
__global__ void __launch_bounds__(256) fused_out_kernel(const float* __restrict__ b,
                                                        const int* __restrict__ padp,
                                                        float* __restrict__ out) {
    extern __shared__ char smraw[];
    __nv_bfloat162* smx = (__nv_bfloat162*)smraw;
    __shared__ float rbuf[256];
    __shared__ float sc_g, sc_d, sc_inv0;

    const int row = blockIdx.x;
    const int tid = threadIdx.x;
    const int pad = *padp;

    // cache Mx row (VO bf16 = 4000 uint4)
    const uint4* src = (const uint4*)(g_Mx + (size_t)row * VO);
    uint4* dst = (uint4*)smraw;
    #pragma unroll 4
    for (int i = tid; i < VO / 8; i += 256) dst[i] = src[i];

    if (tid == 0) {
        float ss = g_ss[row];
        float db = g_db[row];
        float xn = g_xnorm[row];
        float mxn = fmaxf(sqrtf(ss), 1e-15f);
        float art = atanhf(fminf(xn, 1.f - 1e-7f));
        float t = tanhf(mxn / xn * art);
        float alpha = t / mxn;
        float xy = alpha * db;
        float x2 = t * t;
        float y2 = g_y2;
        float Ac = 1.f + 2.f * xy + y2;
        float Bc = 1.f - x2;
        float den = fmaxf(1.f + 2.f * xy + x2 * y2, 1e-15f);
        float nl2 = (Ac * Ac * t * t + 2.f * Ac * Bc * alpha * db + Bc * Bc * y2) / (den * den);
        float nl = fmaxf(sqrtf(nl2), 1e-15f);
        float sc = (nl > 0.996f) ? (0.996f / nl) : 1.f;
        sc_g = sc * Ac * alpha / den;
        sc_d = sc * Bc / den;
        sc_inv0 = 1.f - g_pcopy[row];
    }
    __syncthreads();

    const float gamma = sc_g, delta = sc_d;
    const float2* b2 = (const float2*)b;

    // pass 1: sum of exp (exact: logits bounded by projection, no max shift)
    float s = 0.f;
    for (int i = tid; i < VO / 2; i += 256) {
        __nv_bfloat162 m = smx[i];
        float2 bv = b2[i];
        float l0 = gamma * __bfloat162float(m.x) + delta * bv.x;
        float l1 = gamma * __bfloat162float(m.y) + delta * bv.y;
        float e0 = __expf(l0);
        float e1 = __expf(l1);
        int base = i * 2;
        if (pad == base) e0 = 0.f;
        if (pad == base + 1) e1 = 0.f;
        s += e0 + e1;
    }
    s = block_reduce_sum(s, rbuf);
    const float inv = sc_inv0 / s;

    // pass 2: write probabilities
    float2* o2 = (float2*)(out + (size_t)row * OC);
    for (int i = tid; i < VO / 2; i += 256) {
        __nv_bfloat162 m = smx[i];
        float2 bv = b2[i];
        float l0 = gamma * __bfloat162float(m.x) + delta * bv.x;
        float l1 = gamma * __bfloat162float(m.y) + delta * bv.y;
        float2 r;
        r.x = __expf(l0) * inv;
        r.y = __expf(l1) * inv;
        int base = i * 2;
        if (pad == base) r.x = 0.f;
        if (pad == base + 1) r.y = 0.f;
        o2[i] = r;
    }
}

// ------- copy branch: per-batch (64x512)@(512x500) small GEMM -------
#define SCH 32
__global__ void __launch_bounds__(256) copy_kernel(const float* __restrict__ attn,
                                                   const float* __restrict__ src,
                                                   float* __restrict__ out) {
    __shared__ float sa[64][SCH + 1];
    __shared__ float sbuf[SCH][128];
    __shared__ float spc[64];
    const int bb = blockIdx.y;
    const int c0 = blockIdx.x * 128;
    const int tid = threadIdx.x;
    const int tx = tid % 16;
    const int ty = tid / 16;

    if (tid < 64) spc[tid] = g_pcopy[tid * NB + bb];

    float acc[4][8] = {};
    for (int s0 = 0; s0 < SL; s0 += SCH) {
        __syncthreads();
        for (int i = tid; i < 64 * (SCH / 4); i += 256) {
            int t = i / (SCH / 4);
            int sv = i % (SCH / 4);
            float4 v = *(const float4*)(attn + (size_t)(t * NB + bb) * SL + s0 + sv * 4);
            float pc = spc[t];
            sa[t][sv * 4 + 0] = v.x * pc;
            sa[t][sv * 4 + 1] = v.y * pc;
            sa[t][sv * 4 + 2] = v.z * pc;
            sa[t][sv * 4 + 3] = v.w * pc;
        }
        for (int i = tid; i < SCH * 128; i += 256) {
            int s = i / 128;
            int c = i % 128;
            int cg = c0 + c;
            sbuf[s][c] = (cg < CV) ? src[(size_t)(s0 + s) * (NB * CV) + bb * CV + cg] : 0.f;
        }
        __syncthreads();
        #pragma unroll 8
        for (int s = 0; s < SCH; s++) {
            float a[4], bf[8];
            #pragma unroll
            for (int i = 0; i < 4; i++) a[i] = sa[ty * 4 + i][s];
            #pragma unroll
            for (int j = 0; j < 8; j++) bf[j] = sbuf[s][tx * 8 + j];
            #pragma unroll
            for (int i = 0; i < 4; i++)
                #pragma unroll
                for (int j = 0; j < 8; j++)
                    acc[i][j] = fmaf(a[i], bf[j], acc[i][j]);
        }
    }
    #pragma unroll
    for (int i = 0; i < 4; i++) {
        int t = ty * 4 + i;
        #pragma unroll
        for (int j = 0; j < 8; j++) {
            int c = c0 + tx * 8 + j;
            if (c < CV)
                out[(size_t)(t * NB + bb) * OC + VO + c] = acc[i][j];
        }
    }
}

// ---------------- launch ----------------
extern "C" void kernel_launch(void* const* d_in, const int* in_sizes, int n_in,
                              void* d_out, int out_size) {
    const float* hidden = (const float*)d_in[0];
    const float* attn   = (const float*)d_in[1];
    const float* srcm   = (const float*)d_in[2];
    const float* W      = (const float*)d_in[3];
    const float* b      = (const float*)d_in[4];
    const float* Wc     = (const float*)d_in[5];
    const float* bc     = (const float*)d_in[6];
    const int*   pad    = (const int*)d_in[7];
    float* out = (float*)d_out;

    cudaFuncSetAttribute(gemm_mma_kernel,
                         cudaFuncAttributeMaxDynamicSharedMemorySize, SMEM_GEMM);
    cudaFuncSetAttribute(fused_out_kernel,
                         cudaFuncAttributeMaxDynamicSharedMemorySize, VO * 2);

    __nv_bfloat16* hid_bf;
    __nv_bfloat16* W_bf;
    cudaGetSymbolAddress((void**)&hid_bf, g_hid_bf);
    cudaGetSymbolAddress((void**)&W_bf, g_W_bf);

    conv_bf16_kernel<<<(NR * DK / 4 + 255) / 256, 256>>>(hidden, hid_bf, NR * DK / 4);
    conv_bf16_kernel<<<(VO * DK / 4 + 255) / 256, 256>>>(W, W_bf, VO * DK / 4);
    bnorm_kernel<<<1, 256>>>(b);
    row_prep_kernel<<<NR, 256>>>(hidden, Wc, bc);
    gemm_mma_kernel<<<dim3(VO / BN, NR / BM), 256, SMEM_GEMM>>>(b);
    fused_out_kernel<<<NR, 256, VO * 2>>>(b, pad, out);
    copy_kernel<<<dim3((CV + 127) / 128, NB), 256>>>(attn, srcm, out);
}